// round 1
// baseline (speedup 1.0000x reference)
#include <cuda_runtime.h>

#define NN   2048
#define TT   32
#define FIN  5
#define HH   64
#define G4   256     // 4*H gates
#define NB   16      // nodes per block
#define NBLK 128     // NN/NB
#define NWRD 64      // NN/32

// -------- scratch (device globals; no allocation allowed) --------
__device__ float    g_h0seq[TT * NBLK * HH * NB];   // [t][blk][j][nb] tile layout, 16.8MB
__device__ float    g_x[NN * HH];
__device__ unsigned g_adjT[NN * NWRD];              // [dst j][word c] bits over src i
__device__ float    g_h1[NN * 16];
__device__ float    g_s1[NN], g_d1[NN];
__device__ float    g_o1[NN * 16];
__device__ float    g_h2[NN * HH];
__device__ float    g_s2[NN], g_d2[NN];

// -------- helpers --------
__device__ __forceinline__ unsigned long long pack2(float x, float y) {
    unsigned long long d;
    asm("mov.b64 %0, {%1,%2};" : "=l"(d) : "f"(x), "f"(y));
    return d;
}
__device__ __forceinline__ unsigned long long ffma2(unsigned long long a, unsigned long long b,
                                                    unsigned long long c) {
    unsigned long long d;
    asm("fma.rn.f32x2 %0, %1, %2, %3;" : "=l"(d) : "l"(a), "l"(b), "l"(c));
    return d;
}
__device__ __forceinline__ float sigm(float x)   { return 1.f / (1.f + __expf(-x)); }
__device__ __forceinline__ float tanh_f(float x) { return 1.f - 2.f / (__expf(2.f * x) + 1.f); }
__device__ __forceinline__ float lrelu(float x)  { return x >= 0.f ? x : 0.2f * x; }

// ================= adjacency bitmask =================
// adj[i][j] = (rel_mask[i][j]==0) || (i==j); stored transposed by dst column j.
__global__ void k_adj(const float* __restrict__ rel_mask) {
    int j = blockIdx.x * blockDim.x + threadIdx.x;
    if (j >= NN) return;
    for (int c = 0; c < NWRD; ++c) {
        unsigned w = 0;
        #pragma unroll 8
        for (int b = 0; b < 32; ++b) {
            int i = c * 32 + b;
            float v = rel_mask[(size_t)i * NN + j];
            if (v > -1.f || i == j) w |= (1u << b);
        }
        g_adjT[j * NWRD + c] = w;
    }
}

// ================= LSTM layer 0 =================
// thread = gate g (256); each thread accumulates gates for 16 nodes as 8 f32x2 pairs.
extern __shared__ float smem[];

__global__ void __launch_bounds__(256, 1) k_lstm0(
    const float* __restrict__ inputs,
    const float* __restrict__ w_ih, const float* __restrict__ w_hh,
    const float* __restrict__ b_ih, const float* __restrict__ b_hh)
{
    float* wih  = smem;                  // [FIN][256]
    float* whh  = wih + FIN * G4;        // [64][256]
    float* bias = whh + HH * G4;         // [256]
    float* xs   = bias + G4;             // [32][5][16]
    float* hT   = xs + TT * FIN * NB;    // [64][16]
    float* cT   = hT + HH * NB;          // [64][16]
    float* gbuf = cT + HH * NB;          // [256][18]

    int tid = threadIdx.x;
    int n0  = blockIdx.x * NB;

    for (int idx = tid; idx < G4 * FIN; idx += 256)
        wih[(idx % FIN) * G4 + idx / FIN] = w_ih[idx];
    for (int idx = tid; idx < G4 * HH; idx += 256)
        whh[(idx % HH) * G4 + idx / HH] = w_hh[idx];
    if (tid < G4) bias[tid] = b_ih[tid] + b_hh[tid];
    for (int idx = tid; idx < NB * TT * FIN; idx += 256) {
        int nb = idx / (TT * FIN);
        int r  = idx % (TT * FIN);
        xs[r * NB + nb] = inputs[(size_t)(n0 + nb) * TT * FIN + r];
    }
    for (int idx = tid; idx < HH * NB; idx += 256) { hT[idx] = 0.f; cT[idx] = 0.f; }
    __syncthreads();

    for (int t = 0; t < TT; ++t) {
        float bv = bias[tid];
        unsigned long long acc[8];
        unsigned long long bp = pack2(bv, bv);
        #pragma unroll
        for (int p = 0; p < 8; ++p) acc[p] = bp;

        const float* xrow = &xs[t * FIN * NB];
        #pragma unroll
        for (int f = 0; f < FIN; ++f) {
            float wv = wih[f * G4 + tid];
            unsigned long long w2 = pack2(wv, wv);
            const ulonglong2* hp = (const ulonglong2*)(xrow + f * NB);
            ulonglong2 p0 = hp[0], p1 = hp[1], p2 = hp[2], p3 = hp[3];
            acc[0] = ffma2(w2, p0.x, acc[0]); acc[1] = ffma2(w2, p0.y, acc[1]);
            acc[2] = ffma2(w2, p1.x, acc[2]); acc[3] = ffma2(w2, p1.y, acc[3]);
            acc[4] = ffma2(w2, p2.x, acc[4]); acc[5] = ffma2(w2, p2.y, acc[5]);
            acc[6] = ffma2(w2, p3.x, acc[6]); acc[7] = ffma2(w2, p3.y, acc[7]);
        }
        #pragma unroll 8
        for (int k = 0; k < HH; ++k) {
            float wv = whh[k * G4 + tid];
            unsigned long long w2 = pack2(wv, wv);
            const ulonglong2* hp = (const ulonglong2*)(hT + k * NB);
            ulonglong2 p0 = hp[0], p1 = hp[1], p2 = hp[2], p3 = hp[3];
            acc[0] = ffma2(w2, p0.x, acc[0]); acc[1] = ffma2(w2, p0.y, acc[1]);
            acc[2] = ffma2(w2, p1.x, acc[2]); acc[3] = ffma2(w2, p1.y, acc[3]);
            acc[4] = ffma2(w2, p2.x, acc[4]); acc[5] = ffma2(w2, p2.y, acc[5]);
            acc[6] = ffma2(w2, p3.x, acc[6]); acc[7] = ffma2(w2, p3.y, acc[7]);
        }
        #pragma unroll
        for (int p = 0; p < 8; ++p)
            *(unsigned long long*)&gbuf[tid * 18 + 2 * p] = acc[p];
        __syncthreads();

        #pragma unroll
        for (int q = 0; q < 4; ++q) {
            int nb = tid & 15;
            int j  = (tid >> 4) + q * 16;
            float gi = gbuf[(j      ) * 18 + nb];
            float gf = gbuf[(j +  64) * 18 + nb];
            float gg = gbuf[(j + 128) * 18 + nb];
            float go = gbuf[(j + 192) * 18 + nb];
            float c  = sigm(gf) * cT[j * NB + nb] + sigm(gi) * tanh_f(gg);
            float h  = sigm(go) * tanh_f(c);
            cT[j * NB + nb] = c;
            hT[j * NB + nb] = h;
            g_h0seq[(((size_t)t * NBLK + blockIdx.x) * HH + j) * NB + nb] = h;
        }
        __syncthreads();
    }
}

// ================= LSTM layer 1 =================
__global__ void __launch_bounds__(256, 1) k_lstm1(
    const float* __restrict__ w_ih, const float* __restrict__ w_hh,
    const float* __restrict__ b_ih, const float* __restrict__ b_hh)
{
    float* wih  = smem;                 // [64][256]
    float* whh  = wih + HH * G4;        // [64][256]
    float* bias = whh + HH * G4;        // [256]
    float* hin  = bias + G4;            // [64][16]
    float* hT   = hin + HH * NB;
    float* cT   = hT + HH * NB;
    float* gbuf = cT + HH * NB;         // [256][18]

    int tid = threadIdx.x;
    int n0  = blockIdx.x * NB;

    for (int idx = tid; idx < G4 * HH; idx += 256) {
        wih[(idx % HH) * G4 + idx / HH] = w_ih[idx];
        whh[(idx % HH) * G4 + idx / HH] = w_hh[idx];
    }
    if (tid < G4) bias[tid] = b_ih[tid] + b_hh[tid];
    for (int idx = tid; idx < HH * NB; idx += 256) { hT[idx] = 0.f; cT[idx] = 0.f; }

    // prefetch t=0 tile
    float pf[4];
    {
        const float* src = &g_h0seq[((size_t)0 * NBLK + blockIdx.x) * HH * NB];
        #pragma unroll
        for (int q = 0; q < 4; ++q) pf[q] = src[q * 256 + tid];
    }
    __syncthreads();

    for (int t = 0; t < TT; ++t) {
        #pragma unroll
        for (int q = 0; q < 4; ++q) hin[q * 256 + tid] = pf[q];
        __syncthreads();
        if (t + 1 < TT) {
            const float* src = &g_h0seq[((size_t)(t + 1) * NBLK + blockIdx.x) * HH * NB];
            #pragma unroll
            for (int q = 0; q < 4; ++q) pf[q] = src[q * 256 + tid];
        }

        float bv = bias[tid];
        unsigned long long acc[8];
        unsigned long long bp = pack2(bv, bv);
        #pragma unroll
        for (int p = 0; p < 8; ++p) acc[p] = bp;

        #pragma unroll 8
        for (int k = 0; k < HH; ++k) {
            float wv = wih[k * G4 + tid];
            unsigned long long w2 = pack2(wv, wv);
            const ulonglong2* hp = (const ulonglong2*)(hin + k * NB);
            ulonglong2 p0 = hp[0], p1 = hp[1], p2 = hp[2], p3 = hp[3];
            acc[0] = ffma2(w2, p0.x, acc[0]); acc[1] = ffma2(w2, p0.y, acc[1]);
            acc[2] = ffma2(w2, p1.x, acc[2]); acc[3] = ffma2(w2, p1.y, acc[3]);
            acc[4] = ffma2(w2, p2.x, acc[4]); acc[5] = ffma2(w2, p2.y, acc[5]);
            acc[6] = ffma2(w2, p3.x, acc[6]); acc[7] = ffma2(w2, p3.y, acc[7]);
        }
        #pragma unroll 8
        for (int k = 0; k < HH; ++k) {
            float wv = whh[k * G4 + tid];
            unsigned long long w2 = pack2(wv, wv);
            const ulonglong2* hp = (const ulonglong2*)(hT + k * NB);
            ulonglong2 p0 = hp[0], p1 = hp[1], p2 = hp[2], p3 = hp[3];
            acc[0] = ffma2(w2, p0.x, acc[0]); acc[1] = ffma2(w2, p0.y, acc[1]);
            acc[2] = ffma2(w2, p1.x, acc[2]); acc[3] = ffma2(w2, p1.y, acc[3]);
            acc[4] = ffma2(w2, p2.x, acc[4]); acc[5] = ffma2(w2, p2.y, acc[5]);
            acc[6] = ffma2(w2, p3.x, acc[6]); acc[7] = ffma2(w2, p3.y, acc[7]);
        }
        #pragma unroll
        for (int p = 0; p < 8; ++p)
            *(unsigned long long*)&gbuf[tid * 18 + 2 * p] = acc[p];
        __syncthreads();

        #pragma unroll
        for (int q = 0; q < 4; ++q) {
            int nb = tid & 15;
            int j  = (tid >> 4) + q * 16;
            float gi = gbuf[(j      ) * 18 + nb];
            float gf = gbuf[(j +  64) * 18 + nb];
            float gg = gbuf[(j + 128) * 18 + nb];
            float go = gbuf[(j + 192) * 18 + nb];
            float c  = sigm(gf) * cT[j * NB + nb] + sigm(gi) * tanh_f(gg);
            float h  = sigm(go) * tanh_f(c);
            cT[j * NB + nb] = c;
            hT[j * NB + nb] = h;
            if (t == TT - 1) g_x[(size_t)(n0 + nb) * HH + j] = h;
        }
        __syncthreads();
    }
}

// ================= GAT projections =================
__global__ void k_gprep1(const float* __restrict__ W, const float* __restrict__ as_,
                         const float* __restrict__ ad_)
{
    __shared__ float Ws[64 * 16], asv[16], adv[16];
    int tid = threadIdx.x;
    for (int i = tid; i < 64 * 16; i += 128) Ws[i] = W[i];
    if (tid < 16) { asv[tid] = as_[tid]; adv[tid] = ad_[tid]; }
    __syncthreads();
    int n = blockIdx.x * 128 + tid;
    float xr[64];
    #pragma unroll
    for (int k = 0; k < 64; k += 4) {
        float4 v = *(const float4*)&g_x[(size_t)n * 64 + k];
        xr[k] = v.x; xr[k + 1] = v.y; xr[k + 2] = v.z; xr[k + 3] = v.w;
    }
    float s = 0.f, dd = 0.f;
    #pragma unroll
    for (int jj = 0; jj < 16; ++jj) {
        float hv = 0.f;
        #pragma unroll
        for (int k = 0; k < 64; ++k) hv += xr[k] * Ws[k * 16 + jj];
        g_h1[n * 16 + jj] = hv;
        s += hv * asv[jj];
        dd += hv * adv[jj];
    }
    g_s1[n] = s; g_d1[n] = dd;
}

__global__ void k_gprep2(const float* __restrict__ W, const float* __restrict__ as_,
                         const float* __restrict__ ad_)
{
    __shared__ float Ws[16 * 64], asv[64], adv[64];
    int tid = threadIdx.x;
    for (int i = tid; i < 16 * 64; i += 128) Ws[i] = W[i];
    if (tid < 64) { asv[tid] = as_[tid]; adv[tid] = ad_[tid]; }
    __syncthreads();
    int n = blockIdx.x * 128 + tid;
    float orr[16];
    #pragma unroll
    for (int k = 0; k < 16; k += 4) {
        float4 v = *(const float4*)&g_o1[(size_t)n * 16 + k];
        orr[k] = v.x; orr[k + 1] = v.y; orr[k + 2] = v.z; orr[k + 3] = v.w;
    }
    float s = 0.f, dd = 0.f;
    #pragma unroll
    for (int jj = 0; jj < 64; ++jj) {
        float hv = 0.f;
        #pragma unroll
        for (int k = 0; k < 16; ++k) hv += orr[k] * Ws[k * 64 + jj];
        g_h2[(size_t)n * 64 + jj] = hv;
        s += hv * asv[jj];
        dd += hv * adv[jj];
    }
    g_s2[n] = s; g_d2[n] = dd;
}

// ================= GAT softmax-aggregate layers =================
// warp per destination column j; softmax over sources i (axis 0), online then apply.
__global__ void __launch_bounds__(256) k_gmain1(const float* __restrict__ b1)
{
    int warp = threadIdx.x >> 5, lane = threadIdx.x & 31;
    int j = blockIdx.x * 8 + warp;
    float dj = g_d1[j];
    const unsigned* adjw = &g_adjT[j * NWRD];

    float m = -1e30f, ssum = 0.f;
    for (int c = lane; c < NWRD; c += 32) {
        unsigned w = adjw[c];
        while (w) {
            int b = __ffs(w) - 1; w &= w - 1;
            int i = c * 32 + b;
            float e = lrelu(g_s1[i] + dj);
            if (e > m) { ssum = ssum * __expf(m - e) + 1.f; m = e; }
            else         ssum += __expf(e - m);
        }
    }
    float M = m;
    #pragma unroll
    for (int o = 16; o; o >>= 1) M = fmaxf(M, __shfl_xor_sync(~0u, M, o));
    ssum *= __expf(m - M);
    #pragma unroll
    for (int o = 16; o; o >>= 1) ssum += __shfl_xor_sync(~0u, ssum, o);
    float inv = 1.f / ssum;

    int h = lane & 15, half = lane >> 4;
    float acc = 0.f;
    for (int c = half * 32; c < half * 32 + 32; ++c) {
        unsigned w = adjw[c];
        while (w) {
            int b = __ffs(w) - 1; w &= w - 1;
            int i = c * 32 + b;
            float e = lrelu(g_s1[i] + dj);
            float al = __expf(e - M) * inv;
            acc += al * g_h1[i * 16 + h];
        }
    }
    acc += __shfl_xor_sync(~0u, acc, 16);
    if (lane < 16) {
        float v = acc + b1[h];
        g_o1[j * 16 + h] = v > 0.f ? v : 0.f;
    }
}

__global__ void __launch_bounds__(256) k_gmain2(const float* __restrict__ b2,
                                                const float* __restrict__ fcW,
                                                const float* __restrict__ fcb,
                                                float* __restrict__ out)
{
    int warp = threadIdx.x >> 5, lane = threadIdx.x & 31;
    int j = blockIdx.x * 8 + warp;
    float dj = g_d2[j];
    const unsigned* adjw = &g_adjT[j * NWRD];

    float m = -1e30f, ssum = 0.f;
    for (int c = lane; c < NWRD; c += 32) {
        unsigned w = adjw[c];
        while (w) {
            int b = __ffs(w) - 1; w &= w - 1;
            int i = c * 32 + b;
            float e = lrelu(g_s2[i] + dj);
            if (e > m) { ssum = ssum * __expf(m - e) + 1.f; m = e; }
            else         ssum += __expf(e - m);
        }
    }
    float M = m;
    #pragma unroll
    for (int o = 16; o; o >>= 1) M = fmaxf(M, __shfl_xor_sync(~0u, M, o));
    ssum *= __expf(m - M);
    #pragma unroll
    for (int o = 16; o; o >>= 1) ssum += __shfl_xor_sync(~0u, ssum, o);
    float inv = 1.f / ssum;

    float a0 = 0.f, a1 = 0.f;
    for (int c = 0; c < NWRD; ++c) {
        unsigned w = adjw[c];
        while (w) {
            int b = __ffs(w) - 1; w &= w - 1;
            int i = c * 32 + b;
            float e = lrelu(g_s2[i] + dj);
            float al = __expf(e - M) * inv;
            a0 += al * g_h2[(size_t)i * 64 + lane];
            a1 += al * g_h2[(size_t)i * 64 + lane + 32];
        }
    }
    float part = (a0 + b2[lane]) * fcW[lane] + (a1 + b2[lane + 32]) * fcW[lane + 32];
    #pragma unroll
    for (int o = 16; o; o >>= 1) part += __shfl_xor_sync(~0u, part, o);
    if (lane == 0) out[j] = lrelu(part + fcb[0]);
}

// ================= launch =================
extern "C" void kernel_launch(void* const* d_in, const int* in_sizes, int n_in,
                              void* d_out, int out_size)
{
    const float* inputs   = (const float*)d_in[0];
    // d_in[1] relation, d_in[3] rel_w_W, d_in[4] rel_w_b: provably unused (adj = mask|diag)
    const float* rel_mask = (const float*)d_in[2];
    const float* w_ih0 = (const float*)d_in[5];
    const float* w_hh0 = (const float*)d_in[6];
    const float* b_ih0 = (const float*)d_in[7];
    const float* b_hh0 = (const float*)d_in[8];
    const float* w_ih1 = (const float*)d_in[9];
    const float* w_hh1 = (const float*)d_in[10];
    const float* b_ih1 = (const float*)d_in[11];
    const float* b_hh1 = (const float*)d_in[12];
    const float* gat1_W  = (const float*)d_in[13];
    const float* gat1_as = (const float*)d_in[14];
    const float* gat1_ad = (const float*)d_in[15];
    const float* gat1_b  = (const float*)d_in[16];
    const float* gat2_W  = (const float*)d_in[17];
    const float* gat2_as = (const float*)d_in[18];
    const float* gat2_ad = (const float*)d_in[19];
    const float* gat2_b  = (const float*)d_in[20];
    const float* fc_W    = (const float*)d_in[21];
    const float* fc_b    = (const float*)d_in[22];

    const int SMEM0 = (FIN * G4 + HH * G4 + G4 + TT * FIN * NB + 2 * HH * NB + G4 * 18) * 4;
    const int SMEM1 = (2 * HH * G4 + G4 + 3 * HH * NB + G4 * 18) * 4;
    cudaFuncSetAttribute(k_lstm0, cudaFuncAttributeMaxDynamicSharedMemorySize, SMEM0);
    cudaFuncSetAttribute(k_lstm1, cudaFuncAttributeMaxDynamicSharedMemorySize, SMEM1);

    k_adj<<<NN / 256, 256>>>(rel_mask);
    k_lstm0<<<NBLK, 256, SMEM0>>>(inputs, w_ih0, w_hh0, b_ih0, b_hh0);
    k_lstm1<<<NBLK, 256, SMEM1>>>(w_ih1, w_hh1, b_ih1, b_hh1);
    k_gprep1<<<NN / 128, 128>>>(gat1_W, gat1_as, gat1_ad);
    k_gmain1<<<NN / 8, 256>>>(gat1_b);
    k_gprep2<<<NN / 128, 128>>>(gat2_W, gat2_as, gat2_ad);
    k_gmain2<<<NN / 8, 256>>>(gat2_b, fc_W, fc_b, (float*)d_out);
}

// round 2
// speedup vs baseline: 1.2070x; 1.2070x over previous
#include <cuda_runtime.h>

#define NN   2048
#define TT   32
#define FIN  5
#define HH   64
#define G4   256     // 4*H gates
#define NB   16      // nodes per block
#define NBLK 128     // NN/NB
#define NWRD 64      // NN/32
#define GST  18      // gbuf row stride (even, padded)

// -------- scratch (device globals; no allocation allowed) --------
__device__ float    g_h0seq[TT * NBLK * HH * NB];   // [t][blk][j][nb]
__device__ unsigned g_adjT[NN * NWRD];              // [dst j][word c] bits over src i
__device__ float    g_h1[NN * 16];
__device__ float    g_s1[NN], g_d1[NN];
__device__ float    g_h2[NN * HH];
__device__ float    g_s2[NN], g_d2[NN];

// -------- helpers --------
__device__ __forceinline__ unsigned long long pack2(float x, float y) {
    unsigned long long d;
    asm("mov.b64 %0, {%1,%2};" : "=l"(d) : "f"(x), "f"(y));
    return d;
}
__device__ __forceinline__ unsigned long long ffma2(unsigned long long a, unsigned long long b,
                                                    unsigned long long c) {
    unsigned long long d;
    asm("fma.rn.f32x2 %0, %1, %2, %3;" : "=l"(d) : "l"(a), "l"(b), "l"(c));
    return d;
}
__device__ __forceinline__ float sigm(float x)   { return 1.f / (1.f + __expf(-x)); }
__device__ __forceinline__ float tanh_f(float x) { return 1.f - 2.f / (__expf(2.f * x) + 1.f); }
__device__ __forceinline__ float lrelu(float x)  { return x >= 0.f ? x : 0.2f * x; }

#define FMA_ROW(wv, rowptr)                                                        \
    {                                                                              \
        unsigned long long w2 = pack2(wv, wv);                                     \
        const ulonglong2* hp = (const ulonglong2*)(rowptr);                        \
        ulonglong2 p0 = hp[0], p1 = hp[1], p2 = hp[2], p3 = hp[3];                 \
        acc[0] = ffma2(w2, p0.x, acc[0]); acc[1] = ffma2(w2, p0.y, acc[1]);        \
        acc[2] = ffma2(w2, p1.x, acc[2]); acc[3] = ffma2(w2, p1.y, acc[3]);        \
        acc[4] = ffma2(w2, p2.x, acc[4]); acc[5] = ffma2(w2, p2.y, acc[5]);        \
        acc[6] = ffma2(w2, p3.x, acc[6]); acc[7] = ffma2(w2, p3.y, acc[7]);        \
    }

extern __shared__ float smem[];

// ================= LSTM layer 0 =================
// 1024 threads: g = tid&255 (gate), kh = tid>>8 (K-quarter). 16 nodes per block.
__global__ void __launch_bounds__(1024, 1) k_lstm0(
    const float* __restrict__ inputs,
    const float* __restrict__ w_ih, const float* __restrict__ w_hh,
    const float* __restrict__ b_ih, const float* __restrict__ b_hh)
{
    float* wih  = smem;                  // [5][256]
    float* whh  = wih + FIN * G4;        // [64][256]
    float* bias = whh + HH * G4;         // [256]
    float* xs   = bias + G4;             // [32][5][16]
    float* hT   = xs + TT * FIN * NB;    // [64][16]
    float* cT   = hT + HH * NB;          // [64][16]
    float* gbuf = cT + HH * NB;          // [4][256][GST]

    int tid = threadIdx.x;
    int g   = tid & 255;
    int kh  = tid >> 8;
    int n0  = blockIdx.x * NB;

    for (int idx = tid; idx < G4 * FIN; idx += 1024)
        wih[(idx % FIN) * G4 + idx / FIN] = w_ih[idx];
    for (int idx = tid; idx < G4 * HH; idx += 1024)
        whh[(idx % HH) * G4 + idx / HH] = w_hh[idx];
    if (tid < G4) bias[tid] = b_ih[tid] + b_hh[tid];
    for (int idx = tid; idx < NB * TT * FIN; idx += 1024) {
        int nb = idx / (TT * FIN);
        int r  = idx % (TT * FIN);
        xs[r * NB + nb] = inputs[(size_t)(n0 + nb) * TT * FIN + r];
    }
    for (int idx = tid; idx < HH * NB; idx += 1024) { hT[idx] = 0.f; cT[idx] = 0.f; }
    __syncthreads();

    // K-quarter row ranges over hh: kh0: 0..12 (plus the 5 x-rows), kh1: 13..29, kh2: 30..46, kh3: 47..63
    int kbeg = (kh == 0) ? 0 : 13 + (kh - 1) * 17;
    int kend = (kh == 0) ? 13 : kbeg + 17;

    for (int t = 0; t < TT; ++t) {
        unsigned long long acc[8];
        if (kh == 0) {
            float bv = bias[g];
            unsigned long long bp = pack2(bv, bv);
            #pragma unroll
            for (int p = 0; p < 8; ++p) acc[p] = bp;
            const float* xrow = &xs[t * FIN * NB];
            #pragma unroll
            for (int f = 0; f < FIN; ++f)
                FMA_ROW(wih[f * G4 + g], xrow + f * NB);
        } else {
            #pragma unroll
            for (int p = 0; p < 8; ++p) acc[p] = 0ull;
        }
        #pragma unroll 4
        for (int k = kbeg; k < kend; ++k)
            FMA_ROW(whh[k * G4 + g], hT + k * NB);

        float* gb = &gbuf[(kh * G4 + g) * GST];
        #pragma unroll
        for (int p = 0; p < 8; ++p)
            *(unsigned long long*)&gb[2 * p] = acc[p];
        __syncthreads();

        // epilogue: 1024 cells = 16 nodes x 64 j, one per thread
        {
            int nb = tid & 15;
            int j  = tid >> 4;
            float gi = 0.f, gf = 0.f, gg = 0.f, go = 0.f;
            #pragma unroll
            for (int q = 0; q < 4; ++q) {
                gi += gbuf[(q * G4 + j      ) * GST + nb];
                gf += gbuf[(q * G4 + j +  64) * GST + nb];
                gg += gbuf[(q * G4 + j + 128) * GST + nb];
                go += gbuf[(q * G4 + j + 192) * GST + nb];
            }
            float c = sigm(gf) * cT[j * NB + nb] + sigm(gi) * tanh_f(gg);
            float h = sigm(go) * tanh_f(c);
            cT[j * NB + nb] = c;
            hT[j * NB + nb] = h;
            g_h0seq[(((size_t)t * NBLK + blockIdx.x) * HH + j) * NB + nb] = h;
        }
        __syncthreads();
    }
}

// ================= LSTM layer 1 (+ fused GAT1 projection) =================
__global__ void __launch_bounds__(1024, 1) k_lstm1(
    const float* __restrict__ w_ih, const float* __restrict__ w_hh,
    const float* __restrict__ b_ih, const float* __restrict__ b_hh,
    const float* __restrict__ gat1_W, const float* __restrict__ gat1_as,
    const float* __restrict__ gat1_ad)
{
    float* wih  = smem;                 // [64][256]
    float* whh  = wih + HH * G4;        // [64][256]
    float* bias = whh + HH * G4;        // [256]
    float* hin  = bias + G4;            // [64][16]
    float* hT   = hin + HH * NB;
    float* cT   = hT + HH * NB;
    float* gbuf = cT + HH * NB;         // [4][256][GST]
    float* W1s  = gbuf + 4 * G4 * GST;  // [64][16]
    float* asv  = W1s + HH * 16;        // [16]
    float* adv  = asv + 16;             // [16]
    float* h1b  = adv + 16;             // [16][16]

    int tid = threadIdx.x;
    int g   = tid & 255;
    int kh  = tid >> 8;
    int n0  = blockIdx.x * NB;

    for (int idx = tid; idx < G4 * HH; idx += 1024) {
        wih[(idx % HH) * G4 + idx / HH] = w_ih[idx];
        whh[(idx % HH) * G4 + idx / HH] = w_hh[idx];
    }
    if (tid < G4) bias[tid] = b_ih[tid] + b_hh[tid];
    if (tid < HH * 16) W1s[tid] = gat1_W[tid];
    if (tid >= 1024 - 32) {
        int l = tid - (1024 - 32);
        if (l < 16) asv[l] = gat1_as[l]; else adv[l - 16] = gat1_ad[l - 16];
    }
    for (int idx = tid; idx < HH * NB; idx += 1024) { hT[idx] = 0.f; cT[idx] = 0.f; }

    // hin <- tile 0 ; pf <- tile 1
    float pf;
    hin[tid] = g_h0seq[((size_t)0 * NBLK + blockIdx.x) * HH * NB + tid];
    pf       = g_h0seq[((size_t)1 * NBLK + blockIdx.x) * HH * NB + tid];
    __syncthreads();

    const float* wsel = (kh < 2) ? wih : whh;
    int kbeg = (kh & 1) * 32;

    for (int t = 0; t < TT; ++t) {
        float* hsel = (kh < 2) ? hin : hT;
        unsigned long long acc[8];
        if (kh == 0) {
            float bv = bias[g];
            unsigned long long bp = pack2(bv, bv);
            #pragma unroll
            for (int p = 0; p < 8; ++p) acc[p] = bp;
        } else {
            #pragma unroll
            for (int p = 0; p < 8; ++p) acc[p] = 0ull;
        }
        #pragma unroll 8
        for (int k = kbeg; k < kbeg + 32; ++k)
            FMA_ROW(wsel[k * G4 + g], hsel + k * NB);

        float* gb = &gbuf[(kh * G4 + g) * GST];
        #pragma unroll
        for (int p = 0; p < 8; ++p)
            *(unsigned long long*)&gb[2 * p] = acc[p];
        __syncthreads();

        // epilogue + double-buffered hin update
        {
            int nb = tid & 15;
            int j  = tid >> 4;
            float gi = 0.f, gf = 0.f, gg = 0.f, go = 0.f;
            #pragma unroll
            for (int q = 0; q < 4; ++q) {
                gi += gbuf[(q * G4 + j      ) * GST + nb];
                gf += gbuf[(q * G4 + j +  64) * GST + nb];
                gg += gbuf[(q * G4 + j + 128) * GST + nb];
                go += gbuf[(q * G4 + j + 192) * GST + nb];
            }
            float c = sigm(gf) * cT[j * NB + nb] + sigm(gi) * tanh_f(gg);
            float h = sigm(go) * tanh_f(c);
            cT[j * NB + nb] = c;
            hT[j * NB + nb] = h;
            if (t + 1 < TT) {
                hin[tid] = pf;
                if (t + 2 < TT)
                    pf = g_h0seq[((size_t)(t + 2) * NBLK + blockIdx.x) * HH * NB + tid];
            }
        }
        __syncthreads();
    }

    // ---- fused GAT1 projection: h1 = hT @ W1, s1 = h1@as, d1 = h1@ad ----
    if (tid < 256) {
        int nb = tid & 15;
        int jj = tid >> 4;
        float hv = 0.f;
        #pragma unroll
        for (int k = 0; k < HH; ++k) hv += hT[k * NB + nb] * W1s[k * 16 + jj];
        h1b[nb * 16 + jj] = hv;
        g_h1[(size_t)(n0 + nb) * 16 + jj] = hv;
    }
    __syncthreads();
    if (tid < 32) {
        int nb = tid & 15;
        const float* av = (tid < 16) ? asv : adv;
        float s = 0.f;
        #pragma unroll
        for (int jj = 0; jj < 16; ++jj) s += h1b[nb * 16 + jj] * av[jj];
        if (tid < 16) g_s1[n0 + nb] = s; else g_d1[n0 + nb] = s;
    }
}

// ================= adjacency bitmask =================
__global__ void k_adj(const float* __restrict__ rel_mask) {
    int j  = blockIdx.x * 256 + threadIdx.x;
    int c0 = blockIdx.y * 4;
    for (int c = c0; c < c0 + 4; ++c) {
        unsigned w = 0;
        #pragma unroll 8
        for (int b = 0; b < 32; ++b) {
            int i = c * 32 + b;
            float v = rel_mask[(size_t)i * NN + j];
            if (v > -1.f || i == j) w |= (1u << b);
        }
        g_adjT[j * NWRD + c] = w;
    }
}

// ================= GAT1 aggregate + fused GAT2 projection =================
__global__ void __launch_bounds__(256) k_gmain1(const float* __restrict__ b1,
                                                const float* __restrict__ W2,
                                                const float* __restrict__ as2,
                                                const float* __restrict__ ad2)
{
    __shared__ float W2s[16 * 64], a2s[64], a2d[64], ob[8][16];
    int tid = threadIdx.x;
    for (int i = tid; i < 16 * 64; i += 256) W2s[i] = W2[i];
    if (tid < 64) { a2s[tid] = as2[tid]; a2d[tid] = ad2[tid]; }
    __syncthreads();

    int warp = tid >> 5, lane = tid & 31;
    int j = blockIdx.x * 8 + warp;
    float dj = g_d1[j];
    const unsigned* adjw = &g_adjT[j * NWRD];

    float m = -1e30f, ssum = 0.f;
    for (int c = lane; c < NWRD; c += 32) {
        unsigned w = adjw[c];
        while (w) {
            int b = __ffs(w) - 1; w &= w - 1;
            int i = c * 32 + b;
            float e = lrelu(g_s1[i] + dj);
            if (e > m) { ssum = ssum * __expf(m - e) + 1.f; m = e; }
            else         ssum += __expf(e - m);
        }
    }
    float M = m;
    #pragma unroll
    for (int o = 16; o; o >>= 1) M = fmaxf(M, __shfl_xor_sync(~0u, M, o));
    ssum *= __expf(m - M);
    #pragma unroll
    for (int o = 16; o; o >>= 1) ssum += __shfl_xor_sync(~0u, ssum, o);
    float inv = 1.f / ssum;

    int h = lane & 15, half = lane >> 4;
    float acc = 0.f;
    for (int c = half * 32; c < half * 32 + 32; ++c) {
        unsigned w = adjw[c];
        while (w) {
            int b = __ffs(w) - 1; w &= w - 1;
            int i = c * 32 + b;
            float e = lrelu(g_s1[i] + dj);
            float al = __expf(e - M) * inv;
            acc += al * g_h1[i * 16 + h];
        }
    }
    acc += __shfl_xor_sync(~0u, acc, 16);
    if (lane < 16) {
        float v = acc + b1[h];
        ob[warp][h] = v > 0.f ? v : 0.f;
    }
    __syncwarp();

    // fused GAT2 projection for this node j
    float o[16];
    #pragma unroll
    for (int k = 0; k < 16; ++k) o[k] = ob[warp][k];
    float hv0 = 0.f, hv1 = 0.f;
    #pragma unroll
    for (int k = 0; k < 16; ++k) {
        hv0 += o[k] * W2s[k * 64 + lane];
        hv1 += o[k] * W2s[k * 64 + lane + 32];
    }
    g_h2[(size_t)j * 64 + lane]      = hv0;
    g_h2[(size_t)j * 64 + lane + 32] = hv1;
    float sp = hv0 * a2s[lane] + hv1 * a2s[lane + 32];
    float dp = hv0 * a2d[lane] + hv1 * a2d[lane + 32];
    #pragma unroll
    for (int oo = 16; oo; oo >>= 1) {
        sp += __shfl_xor_sync(~0u, sp, oo);
        dp += __shfl_xor_sync(~0u, dp, oo);
    }
    if (lane == 0) { g_s2[j] = sp; g_d2[j] = dp; }
}

// ================= GAT2 aggregate + FC =================
__global__ void __launch_bounds__(256) k_gmain2(const float* __restrict__ b2,
                                                const float* __restrict__ fcW,
                                                const float* __restrict__ fcb,
                                                float* __restrict__ out)
{
    int warp = threadIdx.x >> 5, lane = threadIdx.x & 31;
    int j = blockIdx.x * 8 + warp;
    float dj = g_d2[j];
    const unsigned* adjw = &g_adjT[j * NWRD];

    float m = -1e30f, ssum = 0.f;
    for (int c = lane; c < NWRD; c += 32) {
        unsigned w = adjw[c];
        while (w) {
            int b = __ffs(w) - 1; w &= w - 1;
            int i = c * 32 + b;
            float e = lrelu(g_s2[i] + dj);
            if (e > m) { ssum = ssum * __expf(m - e) + 1.f; m = e; }
            else         ssum += __expf(e - m);
        }
    }
    float M = m;
    #pragma unroll
    for (int o = 16; o; o >>= 1) M = fmaxf(M, __shfl_xor_sync(~0u, M, o));
    ssum *= __expf(m - M);
    #pragma unroll
    for (int o = 16; o; o >>= 1) ssum += __shfl_xor_sync(~0u, ssum, o);
    float inv = 1.f / ssum;

    float a0 = 0.f, a1 = 0.f;
    for (int c = 0; c < NWRD; ++c) {
        unsigned w = adjw[c];
        while (w) {
            int b = __ffs(w) - 1; w &= w - 1;
            int i = c * 32 + b;
            float e = lrelu(g_s2[i] + dj);
            float al = __expf(e - M) * inv;
            a0 += al * g_h2[(size_t)i * 64 + lane];
            a1 += al * g_h2[(size_t)i * 64 + lane + 32];
        }
    }
    float part = (a0 + b2[lane]) * fcW[lane] + (a1 + b2[lane + 32]) * fcW[lane + 32];
    #pragma unroll
    for (int o = 16; o; o >>= 1) part += __shfl_xor_sync(~0u, part, o);
    if (lane == 0) out[j] = lrelu(part + fcb[0]);
}

// ================= launch =================
extern "C" void kernel_launch(void* const* d_in, const int* in_sizes, int n_in,
                              void* d_out, int out_size)
{
    const float* inputs   = (const float*)d_in[0];
    // d_in[1] relation, d_in[3] rel_w_W, d_in[4] rel_w_b: provably unused (adj = mask|diag)
    const float* rel_mask = (const float*)d_in[2];
    const float* w_ih0 = (const float*)d_in[5];
    const float* w_hh0 = (const float*)d_in[6];
    const float* b_ih0 = (const float*)d_in[7];
    const float* b_hh0 = (const float*)d_in[8];
    const float* w_ih1 = (const float*)d_in[9];
    const float* w_hh1 = (const float*)d_in[10];
    const float* b_ih1 = (const float*)d_in[11];
    const float* b_hh1 = (const float*)d_in[12];
    const float* gat1_W  = (const float*)d_in[13];
    const float* gat1_as = (const float*)d_in[14];
    const float* gat1_ad = (const float*)d_in[15];
    const float* gat1_b  = (const float*)d_in[16];
    const float* gat2_W  = (const float*)d_in[17];
    const float* gat2_as = (const float*)d_in[18];
    const float* gat2_ad = (const float*)d_in[19];
    const float* gat2_b  = (const float*)d_in[20];
    const float* fc_W    = (const float*)d_in[21];
    const float* fc_b    = (const float*)d_in[22];

    const int SMEM0 = (FIN * G4 + HH * G4 + G4 + TT * FIN * NB + 2 * HH * NB + 4 * G4 * GST) * 4;
    const int SMEM1 = (2 * HH * G4 + G4 + 3 * HH * NB + 4 * G4 * GST + HH * 16 + 32 + 256) * 4;
    cudaFuncSetAttribute(k_lstm0, cudaFuncAttributeMaxDynamicSharedMemorySize, SMEM0);
    cudaFuncSetAttribute(k_lstm1, cudaFuncAttributeMaxDynamicSharedMemorySize, SMEM1);

    k_lstm0<<<NBLK, 1024, SMEM0>>>(inputs, w_ih0, w_hh0, b_ih0, b_hh0);
    k_lstm1<<<NBLK, 1024, SMEM1>>>(w_ih1, w_hh1, b_ih1, b_hh1, gat1_W, gat1_as, gat1_ad);
    k_adj<<<dim3(8, 16), 256>>>(rel_mask);
    k_gmain1<<<NN / 8, 256>>>(gat1_b, gat2_W, gat2_as, gat2_ad);
    k_gmain2<<<NN / 8, 256>>>(gat2_b, fc_W, fc_b, (float*)d_out);
}

// round 3
// speedup vs baseline: 1.3979x; 1.1582x over previous
#include <cuda_runtime.h>

#define NN   2048
#define TT   32
#define FIN  5
#define HH   64
#define G4   256     // 4*H gates
#define NB   16      // nodes per block
#define NBLK 128     // NN/NB
#define NWRD 64      // NN/32
#define GST  18      // gbuf row stride

// -------- scratch --------
__device__ float    g_h0seq[TT * NBLK * HH * NB];   // [t][blk][j][nb]
__device__ unsigned g_adjT[NN * NWRD];
__device__ float    g_h1[NN * 16];
__device__ float    g_s1[NN], g_d1[NN];
__device__ float    g_h2[NN * HH];
__device__ float    g_s2[NN], g_d2[NN];

// -------- helpers --------
__device__ __forceinline__ unsigned long long pack2(float x, float y) {
    unsigned long long d;
    asm("mov.b64 %0, {%1,%2};" : "=l"(d) : "f"(x), "f"(y));
    return d;
}
__device__ __forceinline__ unsigned long long ffma2(unsigned long long a, unsigned long long b,
                                                    unsigned long long c) {
    unsigned long long d;
    asm("fma.rn.f32x2 %0, %1, %2, %3;" : "=l"(d) : "l"(a), "l"(b), "l"(c));
    return d;
}
__device__ __forceinline__ float sigm(float x)   { return 1.f / (1.f + __expf(-x)); }
__device__ __forceinline__ float tanh_f(float x) { return 1.f - 2.f / (__expf(2.f * x) + 1.f); }
__device__ __forceinline__ float lrelu(float x)  { return x >= 0.f ? x : 0.2f * x; }

// thread owns 2 gates (g2, g2+128) x 16 nodes (8 f32x2 pairs each)
#define FMA_ROW2(wp, rowptr)                                                       \
    {                                                                              \
        float2 wv = (wp);                                                          \
        unsigned long long wa = pack2(wv.x, wv.x);                                 \
        unsigned long long wb = pack2(wv.y, wv.y);                                 \
        const ulonglong2* hp = (const ulonglong2*)(rowptr);                        \
        ulonglong2 p0 = hp[0], p1 = hp[1], p2 = hp[2], p3 = hp[3];                 \
        acc[0]  = ffma2(wa, p0.x, acc[0]);  acc[1]  = ffma2(wa, p0.y, acc[1]);     \
        acc[2]  = ffma2(wa, p1.x, acc[2]);  acc[3]  = ffma2(wa, p1.y, acc[3]);     \
        acc[4]  = ffma2(wa, p2.x, acc[4]);  acc[5]  = ffma2(wa, p2.y, acc[5]);     \
        acc[6]  = ffma2(wa, p3.x, acc[6]);  acc[7]  = ffma2(wa, p3.y, acc[7]);     \
        acc[8]  = ffma2(wb, p0.x, acc[8]);  acc[9]  = ffma2(wb, p0.y, acc[9]);     \
        acc[10] = ffma2(wb, p1.x, acc[10]); acc[11] = ffma2(wb, p1.y, acc[11]);    \
        acc[12] = ffma2(wb, p2.x, acc[12]); acc[13] = ffma2(wb, p2.y, acc[13]);    \
        acc[14] = ffma2(wb, p3.x, acc[14]); acc[15] = ffma2(wb, p3.y, acc[15]);    \
    }

extern __shared__ float smem[];

// ================= LSTM layer 0 =================
// 512 threads: g2 = tid&127 (gate pair), kh = tid>>7 (K-quarter).
__global__ void __launch_bounds__(512, 1) k_lstm0(
    const float* __restrict__ inputs,
    const float* __restrict__ w_ih, const float* __restrict__ w_hh,
    const float* __restrict__ b_ih, const float* __restrict__ b_hh)
{
    float* wih  = smem;                  // [5][128][2]
    float* whh  = wih + FIN * G4;        // [64][128][2]
    float* bp   = whh + HH * G4;         // [128][2]
    float* xs   = bp + G4;               // [32][5][16]
    float* hT   = xs + TT * FIN * NB;    // [64][16]
    float* cT   = hT + HH * NB;          // [64][16]
    float* gbuf = cT + HH * NB;          // [4][256][GST]

    int tid = threadIdx.x;
    int g2  = tid & 127;
    int kh  = tid >> 7;
    int n0  = blockIdx.x * NB;

    for (int idx = tid; idx < G4 * FIN; idx += 512) {
        int gate = idx / FIN, k = idx % FIN;
        wih[(k * 128 + (gate & 127)) * 2 + (gate >> 7)] = w_ih[idx];
    }
    for (int idx = tid; idx < G4 * HH; idx += 512) {
        int gate = idx / HH, k = idx % HH;
        whh[(k * 128 + (gate & 127)) * 2 + (gate >> 7)] = w_hh[idx];
    }
    if (tid < G4) bp[(tid & 127) * 2 + (tid >> 7)] = b_ih[tid] + b_hh[tid];
    for (int idx = tid; idx < NB * TT * FIN; idx += 512) {
        int nb = idx / (TT * FIN);
        int r  = idx % (TT * FIN);
        xs[r * NB + nb] = inputs[(size_t)(n0 + nb) * TT * FIN + r];
    }
    for (int idx = tid; idx < HH * NB; idx += 512) { hT[idx] = 0.f; cT[idx] = 0.f; }
    __syncthreads();

    // h-row ranges per quarter: [0,12) [12,29) [29,46) [46,64); x rows on kh0
    int kbeg = (kh == 0) ? 0 : 12 + (kh - 1) * 17;
    int kend = (kh == 0) ? 12 : ((kh == 3) ? 64 : kbeg + 17);

    for (int t = 0; t < TT; ++t) {
        unsigned long long acc[16];
        if (kh == 0) {
            float2 bv = ((const float2*)bp)[g2];
            unsigned long long ba = pack2(bv.x, bv.x), bb = pack2(bv.y, bv.y);
            #pragma unroll
            for (int p = 0; p < 8; ++p) { acc[p] = ba; acc[8 + p] = bb; }
            const float* xrow = &xs[t * FIN * NB];
            #pragma unroll
            for (int f = 0; f < FIN; ++f)
                FMA_ROW2(((const float2*)wih)[f * 128 + g2], xrow + f * NB);
        } else {
            #pragma unroll
            for (int p = 0; p < 16; ++p) acc[p] = 0ull;
        }
        #pragma unroll 2
        for (int k = kbeg; k < kend; ++k)
            FMA_ROW2(((const float2*)whh)[k * 128 + g2], hT + k * NB);

        float* gb0 = &gbuf[(kh * G4 + g2) * GST];
        float* gb1 = &gbuf[(kh * G4 + g2 + 128) * GST];
        #pragma unroll
        for (int p = 0; p < 8; ++p) {
            *(unsigned long long*)&gb0[2 * p] = acc[p];
            *(unsigned long long*)&gb1[2 * p] = acc[8 + p];
        }
        __syncthreads();

        #pragma unroll
        for (int cc = 0; cc < 2; ++cc) {
            int cell = tid + cc * 512;
            int nb = cell & 15;
            int j  = cell >> 4;
            float gi = 0.f, gf = 0.f, gg = 0.f, go = 0.f;
            #pragma unroll
            for (int q = 0; q < 4; ++q) {
                gi += gbuf[(q * G4 + j      ) * GST + nb];
                gf += gbuf[(q * G4 + j +  64) * GST + nb];
                gg += gbuf[(q * G4 + j + 128) * GST + nb];
                go += gbuf[(q * G4 + j + 192) * GST + nb];
            }
            float c = sigm(gf) * cT[j * NB + nb] + sigm(gi) * tanh_f(gg);
            float h = sigm(go) * tanh_f(c);
            cT[j * NB + nb] = c;
            hT[j * NB + nb] = h;
            g_h0seq[(((size_t)t * NBLK + blockIdx.x) * HH + j) * NB + nb] = h;
        }
        __syncthreads();
    }
}

// ================= LSTM layer 1 (+ fused GAT1 projection) =================
__global__ void __launch_bounds__(512, 1) k_lstm1(
    const float* __restrict__ w_ih, const float* __restrict__ w_hh,
    const float* __restrict__ b_ih, const float* __restrict__ b_hh,
    const float* __restrict__ gat1_W, const float* __restrict__ gat1_as,
    const float* __restrict__ gat1_ad)
{
    float* wih  = smem;                 // [64][128][2]
    float* whh  = wih + HH * G4;        // [64][128][2]
    float* bp   = whh + HH * G4;        // [128][2]
    float* hin  = bp + G4;              // [64][16]
    float* hT   = hin + HH * NB;
    float* cT   = hT + HH * NB;
    float* gbuf = cT + HH * NB;         // [4][256][GST]
    // post-loop aliases into gbuf:
    float* W1s = gbuf;                  // [64][16]
    float* asv = W1s + HH * 16;         // [16]
    float* adv = asv + 16;              // [16]
    float* h1b = adv + 16;              // [16][16]

    int tid = threadIdx.x;
    int g2  = tid & 127;
    int kh  = tid >> 7;
    int n0  = blockIdx.x * NB;

    for (int idx = tid; idx < G4 * HH; idx += 512) {
        int gate = idx / HH, k = idx % HH;
        wih[(k * 128 + (gate & 127)) * 2 + (gate >> 7)] = w_ih[idx];
        whh[(k * 128 + (gate & 127)) * 2 + (gate >> 7)] = w_hh[idx];
    }
    if (tid < G4) bp[(tid & 127) * 2 + (tid >> 7)] = b_ih[tid] + b_hh[tid];
    for (int idx = tid; idx < HH * NB; idx += 512) { hT[idx] = 0.f; cT[idx] = 0.f; }

    // hin <- tile 0 ; pf <- tile 1  (2 elems per thread)
    float pf0, pf1;
    hin[tid]       = g_h0seq[((size_t)0 * NBLK + blockIdx.x) * HH * NB + tid];
    hin[tid + 512] = g_h0seq[((size_t)0 * NBLK + blockIdx.x) * HH * NB + tid + 512];
    pf0            = g_h0seq[((size_t)1 * NBLK + blockIdx.x) * HH * NB + tid];
    pf1            = g_h0seq[((size_t)1 * NBLK + blockIdx.x) * HH * NB + tid + 512];
    __syncthreads();

    const float2* wsel = (const float2*)((kh < 2) ? wih : whh);
    int kbeg = (kh & 1) * 32;

    for (int t = 0; t < TT; ++t) {
        const float* hsel = (kh < 2) ? hin : hT;
        unsigned long long acc[16];
        if (kh == 0) {
            float2 bv = ((const float2*)bp)[g2];
            unsigned long long ba = pack2(bv.x, bv.x), bb = pack2(bv.y, bv.y);
            #pragma unroll
            for (int p = 0; p < 8; ++p) { acc[p] = ba; acc[8 + p] = bb; }
        } else {
            #pragma unroll
            for (int p = 0; p < 16; ++p) acc[p] = 0ull;
        }
        #pragma unroll 2
        for (int k = kbeg; k < kbeg + 32; ++k)
            FMA_ROW2(wsel[k * 128 + g2], hsel + k * NB);

        float* gb0 = &gbuf[(kh * G4 + g2) * GST];
        float* gb1 = &gbuf[(kh * G4 + g2 + 128) * GST];
        #pragma unroll
        for (int p = 0; p < 8; ++p) {
            *(unsigned long long*)&gb0[2 * p] = acc[p];
            *(unsigned long long*)&gb1[2 * p] = acc[8 + p];
        }
        __syncthreads();

        #pragma unroll
        for (int cc = 0; cc < 2; ++cc) {
            int cell = tid + cc * 512;
            int nb = cell & 15;
            int j  = cell >> 4;
            float gi = 0.f, gf = 0.f, gg = 0.f, go = 0.f;
            #pragma unroll
            for (int q = 0; q < 4; ++q) {
                gi += gbuf[(q * G4 + j      ) * GST + nb];
                gf += gbuf[(q * G4 + j +  64) * GST + nb];
                gg += gbuf[(q * G4 + j + 128) * GST + nb];
                go += gbuf[(q * G4 + j + 192) * GST + nb];
            }
            float c = sigm(gf) * cT[j * NB + nb] + sigm(gi) * tanh_f(gg);
            float h = sigm(go) * tanh_f(c);
            cT[j * NB + nb] = c;
            hT[j * NB + nb] = h;
        }
        if (t + 1 < TT) {
            hin[tid]       = pf0;
            hin[tid + 512] = pf1;
            if (t + 2 < TT) {
                pf0 = g_h0seq[((size_t)(t + 2) * NBLK + blockIdx.x) * HH * NB + tid];
                pf1 = g_h0seq[((size_t)(t + 2) * NBLK + blockIdx.x) * HH * NB + tid + 512];
            }
        }
        __syncthreads();
    }

    // ---- fused GAT1 projection (aliases gbuf; loop is done with it) ----
    for (int idx = tid; idx < HH * 16; idx += 512) W1s[idx] = gat1_W[idx];
    if (tid < 32) {
        if (tid < 16) asv[tid] = gat1_as[tid];
        else          adv[tid - 16] = gat1_ad[tid - 16];
    }
    __syncthreads();
    if (tid < 256) {
        int nb = tid & 15;
        int jj = tid >> 4;
        float hv = 0.f;
        #pragma unroll
        for (int k = 0; k < HH; ++k) hv += hT[k * NB + nb] * W1s[k * 16 + jj];
        h1b[nb * 16 + jj] = hv;
        g_h1[(size_t)(n0 + nb) * 16 + jj] = hv;
    }
    __syncthreads();
    if (tid < 32) {
        int nb = tid & 15;
        const float* av = (tid < 16) ? asv : adv;
        float s = 0.f;
        #pragma unroll
        for (int jj = 0; jj < 16; ++jj) s += h1b[nb * 16 + jj] * av[jj];
        if (tid < 16) g_s1[n0 + nb] = s; else g_d1[n0 + nb] = s;
    }
}

// ================= adjacency bitmask (split in two launches) =================
__global__ void k_adj(const float* __restrict__ rel_mask, int joff) {
    int j  = joff + blockIdx.x * 256 + threadIdx.x;
    int c0 = blockIdx.y * 4;
    for (int c = c0; c < c0 + 4; ++c) {
        unsigned w = 0;
        #pragma unroll 8
        for (int b = 0; b < 32; ++b) {
            int i = c * 32 + b;
            float v = rel_mask[(size_t)i * NN + j];
            if (v > -1.f || i == j) w |= (1u << b);
        }
        g_adjT[j * NWRD + c] = w;
    }
}

// ================= GAT1 aggregate + fused GAT2 projection =================
__global__ void __launch_bounds__(256) k_gmain1(const float* __restrict__ b1,
                                                const float* __restrict__ W2,
                                                const float* __restrict__ as2,
                                                const float* __restrict__ ad2)
{
    __shared__ float W2s[16 * 64], a2s[64], a2d[64], ob[8][16];
    int tid = threadIdx.x;
    for (int i = tid; i < 16 * 64; i += 256) W2s[i] = W2[i];
    if (tid < 64) { a2s[tid] = as2[tid]; a2d[tid] = ad2[tid]; }
    __syncthreads();

    int warp = tid >> 5, lane = tid & 31;
    int j = blockIdx.x * 8 + warp;
    float dj = g_d1[j];
    const unsigned* adjw = &g_adjT[j * NWRD];

    float m = -1e30f, ssum = 0.f;
    for (int c = lane; c < NWRD; c += 32) {
        unsigned w = adjw[c];
        while (w) {
            int b = __ffs(w) - 1; w &= w - 1;
            int i = c * 32 + b;
            float e = lrelu(g_s1[i] + dj);
            if (e > m) { ssum = ssum * __expf(m - e) + 1.f; m = e; }
            else         ssum += __expf(e - m);
        }
    }
    float M = m;
    #pragma unroll
    for (int o = 16; o; o >>= 1) M = fmaxf(M, __shfl_xor_sync(~0u, M, o));
    ssum *= __expf(m - M);
    #pragma unroll
    for (int o = 16; o; o >>= 1) ssum += __shfl_xor_sync(~0u, ssum, o);
    float inv = 1.f / ssum;

    int h = lane & 15, half = lane >> 4;
    float acc = 0.f;
    for (int c = half * 32; c < half * 32 + 32; ++c) {
        unsigned w = adjw[c];
        while (w) {
            int b = __ffs(w) - 1; w &= w - 1;
            int i = c * 32 + b;
            float e = lrelu(g_s1[i] + dj);
            float al = __expf(e - M) * inv;
            acc += al * g_h1[i * 16 + h];
        }
    }
    acc += __shfl_xor_sync(~0u, acc, 16);
    if (lane < 16) {
        float v = acc + b1[h];
        ob[warp][h] = v > 0.f ? v : 0.f;
    }
    __syncwarp();

    float o[16];
    #pragma unroll
    for (int k = 0; k < 16; ++k) o[k] = ob[warp][k];
    float hv0 = 0.f, hv1 = 0.f;
    #pragma unroll
    for (int k = 0; k < 16; ++k) {
        hv0 += o[k] * W2s[k * 64 + lane];
        hv1 += o[k] * W2s[k * 64 + lane + 32];
    }
    g_h2[(size_t)j * 64 + lane]      = hv0;
    g_h2[(size_t)j * 64 + lane + 32] = hv1;
    float sp = hv0 * a2s[lane] + hv1 * a2s[lane + 32];
    float dp = hv0 * a2d[lane] + hv1 * a2d[lane + 32];
    #pragma unroll
    for (int oo = 16; oo; oo >>= 1) {
        sp += __shfl_xor_sync(~0u, sp, oo);
        dp += __shfl_xor_sync(~0u, dp, oo);
    }
    if (lane == 0) { g_s2[j] = sp; g_d2[j] = dp; }
}

// ================= GAT2 aggregate + FC =================
__global__ void __launch_bounds__(256) k_gmain2(const float* __restrict__ b2,
                                                const float* __restrict__ fcW,
                                                const float* __restrict__ fcb,
                                                float* __restrict__ out)
{
    int warp = threadIdx.x >> 5, lane = threadIdx.x & 31;
    int j = blockIdx.x * 8 + warp;
    float dj = g_d2[j];
    const unsigned* adjw = &g_adjT[j * NWRD];

    float m = -1e30f, ssum = 0.f;
    for (int c = lane; c < NWRD; c += 32) {
        unsigned w = adjw[c];
        while (w) {
            int b = __ffs(w) - 1; w &= w - 1;
            int i = c * 32 + b;
            float e = lrelu(g_s2[i] + dj);
            if (e > m) { ssum = ssum * __expf(m - e) + 1.f; m = e; }
            else         ssum += __expf(e - m);
        }
    }
    float M = m;
    #pragma unroll
    for (int o = 16; o; o >>= 1) M = fmaxf(M, __shfl_xor_sync(~0u, M, o));
    ssum *= __expf(m - M);
    #pragma unroll
    for (int o = 16; o; o >>= 1) ssum += __shfl_xor_sync(~0u, ssum, o);
    float inv = 1.f / ssum;

    float a0 = 0.f, a1 = 0.f;
    for (int c = 0; c < NWRD; ++c) {
        unsigned w = adjw[c];
        while (w) {
            int b = __ffs(w) - 1; w &= w - 1;
            int i = c * 32 + b;
            float e = lrelu(g_s2[i] + dj);
            float al = __expf(e - M) * inv;
            a0 += al * g_h2[(size_t)i * 64 + lane];
            a1 += al * g_h2[(size_t)i * 64 + lane + 32];
        }
    }
    float part = (a0 + b2[lane]) * fcW[lane] + (a1 + b2[lane + 32]) * fcW[lane + 32];
    #pragma unroll
    for (int o = 16; o; o >>= 1) part += __shfl_xor_sync(~0u, part, o);
    if (lane == 0) out[j] = lrelu(part + fcb[0]);
}

// ================= launch =================
extern "C" void kernel_launch(void* const* d_in, const int* in_sizes, int n_in,
                              void* d_out, int out_size)
{
    const float* inputs   = (const float*)d_in[0];
    const float* rel_mask = (const float*)d_in[2];
    const float* w_ih0 = (const float*)d_in[5];
    const float* w_hh0 = (const float*)d_in[6];
    const float* b_ih0 = (const float*)d_in[7];
    const float* b_hh0 = (const float*)d_in[8];
    const float* w_ih1 = (const float*)d_in[9];
    const float* w_hh1 = (const float*)d_in[10];
    const float* b_ih1 = (const float*)d_in[11];
    const float* b_hh1 = (const float*)d_in[12];
    const float* gat1_W  = (const float*)d_in[13];
    const float* gat1_as = (const float*)d_in[14];
    const float* gat1_ad = (const float*)d_in[15];
    const float* gat1_b  = (const float*)d_in[16];
    const float* gat2_W  = (const float*)d_in[17];
    const float* gat2_as = (const float*)d_in[18];
    const float* gat2_ad = (const float*)d_in[19];
    const float* gat2_b  = (const float*)d_in[20];
    const float* fc_W    = (const float*)d_in[21];
    const float* fc_b    = (const float*)d_in[22];

    const int SMEM0 = (FIN * G4 + HH * G4 + G4 + TT * FIN * NB + 2 * HH * NB + 4 * G4 * GST) * 4;
    const int SMEM1 = (2 * HH * G4 + G4 + 3 * HH * NB + 4 * G4 * GST) * 4;
    cudaFuncSetAttribute(k_lstm0, cudaFuncAttributeMaxDynamicSharedMemorySize, SMEM0);
    cudaFuncSetAttribute(k_lstm1, cudaFuncAttributeMaxDynamicSharedMemorySize, SMEM1);

    k_adj<<<dim3(4, 16), 256>>>(rel_mask, 0);
    k_lstm0<<<NBLK, 512, SMEM0>>>(inputs, w_ih0, w_hh0, b_ih0, b_hh0);
    k_adj<<<dim3(4, 16), 256>>>(rel_mask, 1024);
    k_lstm1<<<NBLK, 512, SMEM1>>>(w_ih1, w_hh1, b_ih1, b_hh1, gat1_W, gat1_as, gat1_ad);
    k_gmain1<<<NN / 8, 256>>>(gat1_b, gat2_W, gat2_as, gat2_ad);
    k_gmain2<<<NN / 8, 256>>>(gat2_b, fc_W, fc_b, (float*)d_out);
}

// round 5
// speedup vs baseline: 2.5073x; 1.7936x over previous
#include <cuda_runtime.h>
#include <cuda_bf16.h>

#define NN   2048
#define TT   32
#define FIN  5
#define HH   64
#define NB   16
#define NBLK 128
#define NWRD 64

// ---- smem byte offsets ----
#define ZROWB    272                    // 136 bf16 per Z row (pad for ldmatrix bank spread)
#define STAGE_HI 0                      // W staging hi: 256x128 bf16 = 65536
#define STAGE_LO 65536                  // W staging lo
#define ZHI_OFF  131072                 // Zt hi: 16 x 272B = 4352
#define ZLO_OFF  135424
#define BIAS_OFF 139776                 // 256 f32
#define XS_OFF   140800                 // layer0 xs: 32x5x16 f32 = 10240
#define SMEM_REQ 151040
// after init, staging region is reused: gbuf (256x18 f32 = 18432B) at 0, hfin at 18432
#define GBUF_OFF 0
#define HFIN_OFF 18432

// -------- scratch (device globals) --------
__device__ unsigned long long g_h0hi[(size_t)TT * NBLK * 256]; // [t][blk] 16 nodes x 64 bf16
__device__ unsigned long long g_h0lo[(size_t)TT * NBLK * 256];
__device__ unsigned g_adjT[NN * NWRD];
__device__ float g_h1[NN * 16];
__device__ float g_s1[NN], g_d1[NN];
__device__ float g_h2[NN * HH];
__device__ float g_s2[NN], g_d2[NN];

// -------- helpers --------
__device__ __forceinline__ unsigned smem_u32(const void* p) {
    unsigned a;
    asm("{ .reg .u64 t; cvta.to.shared.u64 t, %1; cvt.u32.u64 %0, t; }" : "=r"(a) : "l"(p));
    return a;
}
__device__ __forceinline__ float sigm(float x)   { return 1.f / (1.f + __expf(-x)); }
__device__ __forceinline__ float tanh_f(float x) { return 1.f - 2.f / (__expf(2.f * x) + 1.f); }
__device__ __forceinline__ float lrelu(float x)  { return x >= 0.f ? x : 0.2f * x; }

__device__ __forceinline__ void split_bf(float v, unsigned short& hi, unsigned short& lo) {
    __nv_bfloat16 h = __float2bfloat16(v);
    __nv_bfloat16 l = __float2bfloat16(v - __bfloat162float(h));
    hi = __bfloat16_as_ushort(h);
    lo = __bfloat16_as_ushort(l);
}
__device__ __forceinline__ void mma_bf16(float* d, const unsigned* a, unsigned b0, unsigned b1) {
    asm volatile(
        "mma.sync.aligned.m16n8k16.row.col.f32.bf16.bf16.f32 "
        "{%0,%1,%2,%3}, {%4,%5,%6,%7}, {%8,%9}, {%0,%1,%2,%3};"
        : "+f"(d[0]), "+f"(d[1]), "+f"(d[2]), "+f"(d[3])
        : "r"(a[0]), "r"(a[1]), "r"(a[2]), "r"(a[3]), "r"(b0), "r"(b1));
}
__device__ __forceinline__ void ldmx4(unsigned addr, unsigned* r) {
    asm volatile("ldmatrix.sync.aligned.m8n8.x4.shared.b16 {%0,%1,%2,%3}, [%4];"
                 : "=r"(r[0]), "=r"(r[1]), "=r"(r[2]), "=r"(r[3]) : "r"(addr));
}

extern __shared__ float4 smemv[];

// ================= HMMA LSTM layer (both layers) =================
// 512 threads = 16 warps; warp w owns gates [16w, 16w+16).
__global__ void __launch_bounds__(512, 1) k_lstm_mma(
    int layer,
    const float* __restrict__ inputs,
    const float* __restrict__ w_ih, const float* __restrict__ w_hh,
    const float* __restrict__ b_ih, const float* __restrict__ b_hh,
    const float* __restrict__ gat1_W, const float* __restrict__ gat1_as,
    const float* __restrict__ gat1_ad)
{
    char* smp = (char*)smemv;
    unsigned sbu = smem_u32(smemv);

    int tid  = threadIdx.x;
    int wid  = tid >> 5;
    int lane = tid & 31;
    int blk  = blockIdx.x;
    int n0   = blk * NB;

    // ---- zero staging + Z ----
    {
        float4 z4 = make_float4(0.f, 0.f, 0.f, 0.f);
        float4* dst = (float4*)smp;
        for (int i = tid; i < 139776 / 16; i += 512) dst[i] = z4;
    }
    __syncthreads();

    // ---- stage W hi/lo ----
    int kw = (layer == 0) ? FIN : HH;
    for (int idx = tid; idx < 256 * kw; idx += 512) {
        int gate = idx / kw, k = idx % kw;
        unsigned short hi, lo;
        split_bf(w_ih[idx], hi, lo);
        *(unsigned short*)(smp + STAGE_HI + (gate * 128 + k) * 2) = hi;
        *(unsigned short*)(smp + STAGE_LO + (gate * 128 + k) * 2) = lo;
    }
    for (int idx = tid; idx < 256 * HH; idx += 512) {
        int gate = idx >> 6, k = idx & 63;
        unsigned short hi, lo;
        split_bf(w_hh[idx], hi, lo);
        *(unsigned short*)(smp + STAGE_HI + (gate * 128 + 64 + k) * 2) = hi;
        *(unsigned short*)(smp + STAGE_LO + (gate * 128 + 64 + k) * 2) = lo;
    }
    float* bias_s = (float*)(smp + BIAS_OFF);
    if (tid < 256) bias_s[tid] = b_ih[tid] + b_hh[tid];

    float* xs = (float*)(smp + XS_OFF);
    uint2 pf = make_uint2(0u, 0u);
    if (layer == 0) {
        for (int idx = tid; idx < NB * TT * FIN; idx += 512) {
            int nb = idx / (TT * FIN);
            int r  = idx % (TT * FIN);
            int t  = r / FIN, f = r % FIN;
            xs[t * 80 + f * 16 + nb] = inputs[(size_t)(n0 + nb) * (TT * FIN) + t * FIN + f];
        }
        if (tid < 80) {
            int f = tid >> 4, nb = tid & 15;
            unsigned short hi, lo;
            split_bf(inputs[(size_t)(n0 + nb) * (TT * FIN) + f], hi, lo);
            *(unsigned short*)(smp + ZHI_OFF + nb * ZROWB + f * 2) = hi;
            *(unsigned short*)(smp + ZLO_OFF + nb * ZROWB + f * 2) = lo;
        }
    } else {
        int half = tid >> 8, r = tid & 255;
        int nb = r >> 4, q = r & 15;
        const uint2* src = (const uint2*)(half ? (void*)g_h0lo : (void*)g_h0hi);
        uint2 v0 = src[(size_t)blk * 256 + r];
        *(uint2*)(smp + (half ? ZLO_OFF : ZHI_OFF) + nb * ZROWB + q * 8) = v0;
        pf = src[((size_t)NBLK + blk) * 256 + r];
    }
    __syncthreads();

    // ---- load W fragments into registers ----
    unsigned whi[8][4], wlo[8][4];
    {
        int g0 = wid * 16 + (lane >> 2);
        int kp = (lane & 3) * 2;
        #pragma unroll
        for (int kt = 0; kt < 8; ++kt) {
            const char* bh = smp + STAGE_HI + (g0 * 128 + kt * 16 + kp) * 2;
            whi[kt][0] = *(const unsigned*)(bh);
            whi[kt][1] = *(const unsigned*)(bh + 2048);
            whi[kt][2] = *(const unsigned*)(bh + 16);
            whi[kt][3] = *(const unsigned*)(bh + 2048 + 16);
            const char* bl = smp + STAGE_LO + (g0 * 128 + kt * 16 + kp) * 2;
            wlo[kt][0] = *(const unsigned*)(bl);
            wlo[kt][1] = *(const unsigned*)(bl + 2048);
            wlo[kt][2] = *(const unsigned*)(bl + 16);
            wlo[kt][3] = *(const unsigned*)(bl + 2048 + 16);
        }
    }
    float bv0 = bias_s[wid * 16 + (lane >> 2)];
    float bv1 = bias_s[wid * 16 + (lane >> 2) + 8];
    __syncthreads();   // staging dead; gbuf may now reuse it

    // ldmatrix per-lane address offsets into Z tiles
    int nrow  = (lane & 7) + ((lane >> 4) << 3);
    int khalf = (lane >> 3) & 1;
    unsigned zhiA = sbu + ZHI_OFF + nrow * ZROWB + khalf * 16;
    unsigned zloA = sbu + ZLO_OFF + nrow * ZROWB + khalf * 16;

    float* gbuf = (float*)(smp + GBUF_OFF);           // [256][18]
    float* hfin = (float*)(smp + HFIN_OFF);           // [64][16] (layer1 only)

    int j0 = tid >> 4, nb0 = tid & 15;                // epilogue cell ids
    float c0 = 0.f, c1 = 0.f;

    #pragma unroll 1
    for (int t = 0; t < TT; ++t) {
        // ---------- phase A: copy prev h to gmem (layer0) + MMA ----------
        if (layer == 0 && t > 0) {
            int half = tid >> 8, r = tid & 255;
            int nb = r >> 4, q = r & 15;
            uint2 v = *(const uint2*)(smp + (half ? ZLO_OFF : ZHI_OFF) + nb * ZROWB + 128 + q * 8);
            ((uint2*)(half ? (void*)g_h0lo : (void*)g_h0hi))
                [((size_t)(t - 1) * NBLK + blk) * 256 + r] = v;
        }

        float accA[2][4], accB[2][4];
        #pragma unroll
        for (int nt = 0; nt < 2; ++nt) {
            accA[nt][0] = bv0; accA[nt][1] = bv0; accA[nt][2] = bv1; accA[nt][3] = bv1;
            accB[nt][0] = 0.f; accB[nt][1] = 0.f; accB[nt][2] = 0.f; accB[nt][3] = 0.f;
        }
        #pragma unroll
        for (int kt = 0; kt < 8; ++kt) {
            unsigned bh[4], bl[4];
            ldmx4(zhiA + kt * 32, bh);
            ldmx4(zloA + kt * 32, bl);
            mma_bf16(accA[0], whi[kt], bh[0], bh[1]);   // Whi*Zhi
            mma_bf16(accA[1], whi[kt], bh[2], bh[3]);
            mma_bf16(accB[0], wlo[kt], bh[0], bh[1]);   // Wlo*Zhi
            mma_bf16(accB[1], wlo[kt], bh[2], bh[3]);
            mma_bf16(accB[0], whi[kt], bl[0], bl[1]);   // Whi*Zlo
            mma_bf16(accB[1], whi[kt], bl[2], bl[3]);
        }
        {
            int ga = wid * 16 + (lane >> 2);
            int cb = (lane & 3) * 2;
            #pragma unroll
            for (int nt = 0; nt < 2; ++nt) {
                float2 v01 = make_float2(accA[nt][0] + accB[nt][0], accA[nt][1] + accB[nt][1]);
                float2 v23 = make_float2(accA[nt][2] + accB[nt][2], accA[nt][3] + accB[nt][3]);
                *(float2*)&gbuf[ga * 18 + nt * 8 + cb]       = v01;
                *(float2*)&gbuf[(ga + 8) * 18 + nt * 8 + cb] = v23;
            }
        }
        __syncthreads();

        // ---------- phase B: epilogue ----------
        float gi0 = gbuf[j0 * 18 + nb0],         gf0 = gbuf[(j0 + 64) * 18 + nb0];
        float gg0 = gbuf[(j0 + 128) * 18 + nb0], go0 = gbuf[(j0 + 192) * 18 + nb0];
        int j1 = j0 + 32;
        float gi1 = gbuf[j1 * 18 + nb0],         gf1 = gbuf[(j1 + 64) * 18 + nb0];
        float gg1 = gbuf[(j1 + 128) * 18 + nb0], go1 = gbuf[(j1 + 192) * 18 + nb0];

        c0 = sigm(gf0) * c0 + sigm(gi0) * tanh_f(gg0);
        c1 = sigm(gf1) * c1 + sigm(gi1) * tanh_f(gg1);
        float h0v = sigm(go0) * tanh_f(c0);
        float h1v = sigm(go1) * tanh_f(c1);

        unsigned short h0h, h0l, h1h, h1l;
        split_bf(h0v, h0h, h0l);
        split_bf(h1v, h1h, h1l);
        *(unsigned short*)(smp + ZHI_OFF + nb0 * ZROWB + (64 + j0) * 2) = h0h;
        *(unsigned short*)(smp + ZLO_OFF + nb0 * ZROWB + (64 + j0) * 2) = h0l;
        *(unsigned short*)(smp + ZHI_OFF + nb0 * ZROWB + (64 + j1) * 2) = h1h;
        *(unsigned short*)(smp + ZLO_OFF + nb0 * ZROWB + (64 + j1) * 2) = h1l;

        if (layer == 0) {
            if (t + 1 < TT && tid < 80) {
                int f = tid >> 4, nb = tid & 15;
                unsigned short hi, lo;
                split_bf(xs[(t + 1) * 80 + f * 16 + nb], hi, lo);
                *(unsigned short*)(smp + ZHI_OFF + nb * ZROWB + f * 2) = hi;
                *(unsigned short*)(smp + ZLO_OFF + nb * ZROWB + f * 2) = lo;
            }
        } else {
            if (t + 1 < TT) {
                int half = tid >> 8, r = tid & 255;
                int nb = r >> 4, q = r & 15;
                *(uint2*)(smp + (half ? ZLO_OFF : ZHI_OFF) + nb * ZROWB + q * 8) = pf;
                if (t + 2 < TT)
                    pf = ((const uint2*)(half ? (void*)g_h0lo : (void*)g_h0hi))
                             [((size_t)(t + 2) * NBLK + blk) * 256 + r];
            } else {
                hfin[j0 * 16 + nb0] = h0v;
                hfin[j1 * 16 + nb0] = h1v;
            }
        }
        __syncthreads();
    }

    if (layer == 0) {
        // final h(T-1) copy
        int half = tid >> 8, r = tid & 255;
        int nb = r >> 4, q = r & 15;
        uint2 v = *(const uint2*)(smp + (half ? ZLO_OFF : ZHI_OFF) + nb * ZROWB + 128 + q * 8);
        ((uint2*)(half ? (void*)g_h0lo : (void*)g_h0hi))
            [((size_t)(TT - 1) * NBLK + blk) * 256 + r] = v;
    } else {
        // fused GAT1 projection
        float* W1s = gbuf;           // reuse
        float* asv = W1s + HH * 16;
        float* adv = asv + 16;
        float* h1b = adv + 16;
        for (int idx = tid; idx < HH * 16; idx += 512) W1s[idx] = gat1_W[idx];
        if (tid < 32) {
            if (tid < 16) asv[tid] = gat1_as[tid];
            else          adv[tid - 16] = gat1_ad[tid - 16];
        }
        __syncthreads();
        if (tid < 256) {
            int nb = tid & 15, jj = tid >> 4;
            float hv = 0.f;
            #pragma unroll
            for (int k = 0; k < HH; ++k) hv += hfin[k * 16 + nb] * W1s[k * 16 + jj];
            h1b[nb * 16 + jj] = hv;
            g_h1[(size_t)(n0 + nb) * 16 + jj] = hv;
        }
        __syncthreads();
        if (tid < 32) {
            int nb = tid & 15;
            const float* av = (tid < 16) ? asv : adv;
            float s = 0.f;
            #pragma unroll
            for (int jj = 0; jj < 16; ++jj) s += h1b[nb * 16 + jj] * av[jj];
            if (tid < 16) g_s1[n0 + nb] = s; else g_d1[n0 + nb] = s;
        }
    }
}

// ================= adjacency bitmask =================
__global__ void k_adj(const float* __restrict__ rel_mask, int joff) {
    int j  = joff + blockIdx.x * 256 + threadIdx.x;
    int c0 = blockIdx.y * 4;
    for (int c = c0; c < c0 + 4; ++c) {
        unsigned w = 0;
        #pragma unroll 8
        for (int b = 0; b < 32; ++b) {
            int i = c * 32 + b;
            float v = rel_mask[(size_t)i * NN + j];
            if (v > -1.f || i == j) w |= (1u << b);
        }
        g_adjT[j * NWRD + c] = w;
    }
}

// ================= GAT1 aggregate + fused GAT2 projection =================
__global__ void __launch_bounds__(256) k_gmain1(const float* __restrict__ b1,
                                                const float* __restrict__ W2,
                                                const float* __restrict__ as2,
                                                const float* __restrict__ ad2)
{
    __shared__ float W2s[16 * 64], a2s[64], a2d[64], ob[8][16];
    int tid = threadIdx.x;
    for (int i = tid; i < 16 * 64; i += 256) W2s[i] = W2[i];
    if (tid < 64) { a2s[tid] = as2[tid]; a2d[tid] = ad2[tid]; }
    __syncthreads();

    int warp = tid >> 5, lane = tid & 31;
    int j = blockIdx.x * 8 + warp;
    float dj = g_d1[j];
    const unsigned* adjw = &g_adjT[j * NWRD];

    float m = -1e30f, ssum = 0.f;
    for (int c = lane; c < NWRD; c += 32) {
        unsigned w = adjw[c];
        while (w) {
            int b = __ffs(w) - 1; w &= w - 1;
            int i = c * 32 + b;
            float e = lrelu(g_s1[i] + dj);
            if (e > m) { ssum = ssum * __expf(m - e) + 1.f; m = e; }
            else         ssum += __expf(e - m);
        }
    }
    float M = m;
    #pragma unroll
    for (int o = 16; o; o >>= 1) M = fmaxf(M, __shfl_xor_sync(~0u, M, o));
    ssum *= __expf(m - M);
    #pragma unroll
    for (int o = 16; o; o >>= 1) ssum += __shfl_xor_sync(~0u, ssum, o);
    float inv = 1.f / ssum;

    float acc[16];
    #pragma unroll
    for (int h = 0; h < 16; ++h) acc[h] = 0.f;
    for (int c = lane * 2; c < lane * 2 + 2; ++c) {
        unsigned w = adjw[c];
        while (w) {
            int b = __ffs(w) - 1; w &= w - 1;
            int i = c * 32 + b;
            float al = __expf(lrelu(g_s1[i] + dj) - M) * inv;
            const float4* hp = (const float4*)&g_h1[i * 16];
            float4 v0 = hp[0], v1 = hp[1], v2 = hp[2], v3 = hp[3];
            acc[0] += al * v0.x; acc[1] += al * v0.y; acc[2]  += al * v0.z; acc[3]  += al * v0.w;
            acc[4] += al * v1.x; acc[5] += al * v1.y; acc[6]  += al * v1.z; acc[7]  += al * v1.w;
            acc[8] += al * v2.x; acc[9] += al * v2.y; acc[10] += al * v2.z; acc[11] += al * v2.w;
            acc[12] += al * v3.x; acc[13] += al * v3.y; acc[14] += al * v3.z; acc[15] += al * v3.w;
        }
    }
    #pragma unroll
    for (int h = 0; h < 16; ++h) {
        #pragma unroll
        for (int o = 16; o; o >>= 1) acc[h] += __shfl_xor_sync(~0u, acc[h], o);
    }
    if (lane < 16) {
        float v = acc[lane] + b1[lane];
        ob[warp][lane] = v > 0.f ? v : 0.f;
    }
    __syncwarp();

    float o[16];
    #pragma unroll
    for (int k = 0; k < 16; ++k) o[k] = ob[warp][k];
    float hv0 = 0.f, hv1 = 0.f;
    #pragma unroll
    for (int k = 0; k < 16; ++k) {
        hv0 += o[k] * W2s[k * 64 + lane];
        hv1 += o[k] * W2s[k * 64 + lane + 32];
    }
    g_h2[(size_t)j * 64 + lane]      = hv0;
    g_h2[(size_t)j * 64 + lane + 32] = hv1;
    float sp = hv0 * a2s[lane] + hv1 * a2s[lane + 32];
    float dp = hv0 * a2d[lane] + hv1 * a2d[lane + 32];
    #pragma unroll
    for (int oo = 16; oo; oo >>= 1) {
        sp += __shfl_xor_sync(~0u, sp, oo);
        dp += __shfl_xor_sync(~0u, dp, oo);
    }
    if (lane == 0) { g_s2[j] = sp; g_d2[j] = dp; }
}

// ================= GAT2 aggregate + FC =================
__global__ void __launch_bounds__(256) k_gmain2(const float* __restrict__ b2,
                                                const float* __restrict__ fcW,
                                                const float* __restrict__ fcb,
                                                float* __restrict__ out)
{
    int warp = threadIdx.x >> 5, lane = threadIdx.x & 31;
    int j = blockIdx.x * 8 + warp;
    float dj = g_d2[j];
    const unsigned* adjw = &g_adjT[j * NWRD];

    float m = -1e30f, ssum = 0.f;
    for (int c = lane; c < NWRD; c += 32) {
        unsigned w = adjw[c];
        while (w) {
            int b = __ffs(w) - 1; w &= w - 1;
            int i = c * 32 + b;
            float e = lrelu(g_s2[i] + dj);
            if (e > m) { ssum = ssum * __expf(m - e) + 1.f; m = e; }
            else         ssum += __expf(e - m);
        }
    }
    float M = m;
    #pragma unroll
    for (int o = 16; o; o >>= 1) M = fmaxf(M, __shfl_xor_sync(~0u, M, o));
    ssum *= __expf(m - M);
    #pragma unroll
    for (int o = 16; o; o >>= 1) ssum += __shfl_xor_sync(~0u, ssum, o);
    float inv = 1.f / ssum;

    float a0 = 0.f, a1 = 0.f;
    for (int c = 0; c < NWRD; ++c) {
        unsigned w = adjw[c];
        while (w) {
            int b = __ffs(w) - 1; w &= w - 1;
            int i = c * 32 + b;
            float e = lrelu(g_s2[i] + dj);
            float al = __expf(e - M) * inv;
            a0 += al * g_h2[(size_t)i * 64 + lane];
            a1 += al * g_h2[(size_t)i * 64 + lane + 32];
        }
    }
    float part = (a0 + b2[lane]) * fcW[lane] + (a1 + b2[lane + 32]) * fcW[lane + 32];
    #pragma unroll
    for (int o = 16; o; o >>= 1) part += __shfl_xor_sync(~0u, part, o);
    if (lane == 0) out[j] = lrelu(part + fcb[0]);
}

// ================= launch =================
extern "C" void kernel_launch(void* const* d_in, const int* in_sizes, int n_in,
                              void* d_out, int out_size)
{
    const float* inputs   = (const float*)d_in[0];
    // d_in[1] relation, d_in[3] rel_w_W, d_in[4] rel_w_b: provably unused (adj = mask|diag)
    const float* rel_mask = (const float*)d_in[2];
    const float* w_ih0 = (const float*)d_in[5];
    const float* w_hh0 = (const float*)d_in[6];
    const float* b_ih0 = (const float*)d_in[7];
    const float* b_hh0 = (const float*)d_in[8];
    const float* w_ih1 = (const float*)d_in[9];
    const float* w_hh1 = (const float*)d_in[10];
    const float* b_ih1 = (const float*)d_in[11];
    const float* b_hh1 = (const float*)d_in[12];
    const float* gat1_W  = (const float*)d_in[13];
    const float* gat1_as = (const float*)d_in[14];
    const float* gat1_ad = (const float*)d_in[15];
    const float* gat1_b  = (const float*)d_in[16];
    const float* gat2_W  = (const float*)d_in[17];
    const float* gat2_as = (const float*)d_in[18];
    const float* gat2_ad = (const float*)d_in[19];
    const float* gat2_b  = (const float*)d_in[20];
    const float* fc_W    = (const float*)d_in[21];
    const float* fc_b    = (const float*)d_in[22];

    cudaFuncSetAttribute(k_lstm_mma, cudaFuncAttributeMaxDynamicSharedMemorySize, SMEM_REQ);

    k_adj<<<dim3(4, 16), 256>>>(rel_mask, 0);
    k_lstm_mma<<<NBLK, 512, SMEM_REQ>>>(0, inputs, w_ih0, w_hh0, b_ih0, b_hh0,
                                        gat1_W, gat1_as, gat1_ad);
    k_adj<<<dim3(4, 16), 256>>>(rel_mask, 1024);
    k_lstm_mma<<<NBLK, 512, SMEM_REQ>>>(1, inputs, w_ih1, w_hh1, b_ih1, b_hh1,
                                        gat1_W, gat1_as, gat1_ad);
    k_gmain1<<<NN / 8, 256>>>(gat1_b, gat2_W, gat2_as, gat2_ad);
    k_gmain2<<<NN / 8, 256>>>(gat2_b, fc_W, fc_b, (float*)d_out);
}